// round 1
// baseline (speedup 1.0000x reference)
#include <cuda_runtime.h>

#define BB    16
#define NN    16384
#define NFPS  512
#define NREG  50
#define TOPK  4
#define NB    128
#define R2C   0.16f
#define FPS_T 1024
#define PPT   16   /* NN / FPS_T */

__device__ int g_fps_idx[BB][NFPS];
__device__ int g_counts[BB][NREG];
__device__ int g_top4[BB][TOPK];

// ---------------------------------------------------------------------------
// Kernel 1: furthest point sampling, one CTA per batch.
// xyz planes cached in shared memory; per-point running min-dist in registers.
// Each iteration: update min-dist, block max-reduce, then atomicMin over all
// indices whose dist equals the max (matches jnp.argmax first-index tie rule).
// Also writes the 512 FPS points into out rows [1024, 1536).
// ---------------------------------------------------------------------------
__global__ void __launch_bounds__(FPS_T, 1)
fps_kernel(const float* __restrict__ pts, float* __restrict__ out)
{
    extern __shared__ float sh[];
    float* sx = sh;
    float* sy = sh + NN;
    float* sz = sh + 2 * NN;
    __shared__ float s_wmax[32];
    __shared__ float s_max;
    __shared__ int   s_amin;
    __shared__ int   s_fps[NFPS];

    const int b = blockIdx.x;
    const int t = threadIdx.x;
    const float* base = pts + (size_t)b * 3 * NN;

    for (int n = t; n < NN; n += FPS_T) {
        sx[n] = base[n];
        sy[n] = base[NN + n];
        sz[n] = base[2 * NN + n];
    }

    float dist[PPT];
#pragma unroll
    for (int k = 0; k < PPT; k++) dist[k] = 1e10f;

    const int lane = t & 31, warp = t >> 5;
    int last = 0;
    if (t == 0) s_amin = 0x7fffffff;
    __syncthreads();

    for (int i = 0; i < NFPS; i++) {
        if (t == 0) s_fps[i] = last;
        const float cx = sx[last], cy = sy[last], cz = sz[last];
        float vmax = -1.0f;
#pragma unroll
        for (int k = 0; k < PPT; k++) {
            const int n = t + (k << 10);
            float dx = sx[n] - cx;
            float dy = sy[n] - cy;
            float dz = sz[n] - cz;
            float d = dx * dx + dy * dy + dz * dz;
            d = fminf(dist[k], d);
            dist[k] = d;
            vmax = fmaxf(vmax, d);
        }
#pragma unroll
        for (int o = 16; o > 0; o >>= 1)
            vmax = fmaxf(vmax, __shfl_xor_sync(0xffffffffu, vmax, o));
        if (lane == 0) s_wmax[warp] = vmax;
        __syncthreads();                       // (1) warp maxes ready
        if (warp == 0) {
            float v = s_wmax[lane];
#pragma unroll
            for (int o = 16; o > 0; o >>= 1)
                v = fmaxf(v, __shfl_xor_sync(0xffffffffu, v, o));
            if (lane == 0) s_max = v;
        }
        __syncthreads();                       // (2) block max ready
        const float m = s_max;
#pragma unroll
        for (int k = 0; k < PPT; k++) {
            if (dist[k] == m) atomicMin(&s_amin, t + (k << 10));
        }
        __syncthreads();                       // (3) argmax ready
        last = s_amin;
        __syncthreads();                       // (4) everyone has read it
        if (t == 0) s_amin = 0x7fffffff;
    }

    __syncthreads();
    if (t < NFPS) {
        const int idx = s_fps[t];
        g_fps_idx[b][t] = idx;
        float* o = out + ((size_t)b * 1536 + 1024 + t) * 3;
        o[0] = sx[idx];
        o[1] = sy[idx];
        o[2] = sz[idx];
    }
}

// ---------------------------------------------------------------------------
// Kernel 2: per-(batch, anchor) ball count.  grid = (NREG, BB)
// d = ((-2*dot) + |a|^2) + |p|^2  — same association as the reference.
// ---------------------------------------------------------------------------
__global__ void count_kernel(const float* __restrict__ pts)
{
    const int a = blockIdx.x, b = blockIdx.y;
    const int t = threadIdx.x;
    const float* base = pts + (size_t)b * 3 * NN;
    const int aidx = g_fps_idx[b][a];
    const float ax = base[aidx], ay = base[NN + aidx], az = base[2 * NN + aidx];
    const float a2 = ax * ax + ay * ay + az * az;

    int cnt = 0;
    for (int n = t; n < NN; n += 256) {
        float x = base[n], y = base[NN + n], z = base[2 * NN + n];
        float dot = ax * x + ay * y + az * z;
        float p2 = x * x + y * y + z * z;
        float d = (-2.0f * dot + a2) + p2;
        cnt += (d < R2C) ? 1 : 0;
    }
    __shared__ int s_c[8];
#pragma unroll
    for (int o = 16; o > 0; o >>= 1) cnt += __shfl_xor_sync(0xffffffffu, cnt, o);
    if ((t & 31) == 0) s_c[t >> 5] = cnt;
    __syncthreads();
    if (t == 0) {
        int s = 0;
#pragma unroll
        for (int w = 0; w < 8; w++) s += s_c[w];
        g_counts[b][a] = min(s, 1000);
    }
}

// ---------------------------------------------------------------------------
// Kernel 3: top-4 anchors by count (ties -> lower index).  grid = BB
// ---------------------------------------------------------------------------
__global__ void top4_kernel()
{
    const int b = blockIdx.x;
    if (threadIdx.x != 0) return;
    int cnts[NREG];
    for (int a = 0; a < NREG; a++) cnts[a] = g_counts[b][a];
    for (int j = 0; j < TOPK; j++) {
        int best = -1, bi = 0;
        for (int a = 0; a < NREG; a++)
            if (cnts[a] > best) { best = cnts[a]; bi = a; }   // strict > keeps lowest index on tie
        g_top4[b][j] = g_fps_idx[b][bi];
        cnts[bi] = -2;
    }
}

// ---------------------------------------------------------------------------
// Kernel 4: 128-NN per (query, batch).  grid = (TOPK, BB)
// Sequential argmin extraction reproduces top_k's ascending order with
// lower-index tie break.  Writes roi1 rows [0,512) and roi2 rows [512,1024).
// ---------------------------------------------------------------------------
__global__ void __launch_bounds__(FPS_T, 1)
knn_kernel(const float* __restrict__ pts, float* __restrict__ out)
{
    const int q = blockIdx.x, b = blockIdx.y;
    const int t = threadIdx.x;
    const float* base = pts + (size_t)b * 3 * NN;
    __shared__ float s_wmin[32];
    __shared__ float s_min;
    __shared__ int   s_amin;

    const int qidx = g_top4[b][q];
    const float qx = base[qidx], qy = base[NN + qidx], qz = base[2 * NN + qidx];
    const float q2 = qx * qx + qy * qy + qz * qz;

    float dist[PPT];
#pragma unroll
    for (int k = 0; k < PPT; k++) {
        const int n = t + (k << 10);
        float x = base[n], y = base[NN + n], z = base[2 * NN + n];
        float dot = qx * x + qy * y + qz * z;
        float p2 = x * x + y * y + z * z;
        dist[k] = (-2.0f * dot + q2) + p2;
    }

    const int lane = t & 31, warp = t >> 5;
    if (t == 0) s_amin = 0x7fffffff;
    __syncthreads();

    for (int j = 0; j < NB; j++) {
        float vmin = 3.4e38f;
#pragma unroll
        for (int k = 0; k < PPT; k++) vmin = fminf(vmin, dist[k]);
#pragma unroll
        for (int o = 16; o > 0; o >>= 1)
            vmin = fminf(vmin, __shfl_xor_sync(0xffffffffu, vmin, o));
        if (lane == 0) s_wmin[warp] = vmin;
        __syncthreads();
        if (warp == 0) {
            float v = s_wmin[lane];
#pragma unroll
            for (int o = 16; o > 0; o >>= 1)
                v = fminf(v, __shfl_xor_sync(0xffffffffu, v, o));
            if (lane == 0) s_min = v;
        }
        __syncthreads();
        const float m = s_min;
#pragma unroll
        for (int k = 0; k < PPT; k++)
            if (dist[k] == m) atomicMin(&s_amin, t + (k << 10));
        __syncthreads();
        const int win = s_amin;
#pragma unroll
        for (int k = 0; k < PPT; k++)
            if ((t + (k << 10)) == win) dist[k] = 3.4e38f;
        if (t == 0) {
            float x = base[win], y = base[NN + win], z = base[2 * NN + win];
            const size_t r = (size_t)b * 1536 + (size_t)q * NB + j;
            float* o1 = out + r * 3;
            o1[0] = x; o1[1] = y; o1[2] = z;
            float* o2 = out + (r + 512) * 3;
            o2[0] = x; o2[1] = y; o2[2] = z;
        }
        __syncthreads();
        if (t == 0) s_amin = 0x7fffffff;
    }
}

// ---------------------------------------------------------------------------
extern "C" void kernel_launch(void* const* d_in, const int* in_sizes, int n_in,
                              void* d_out, int out_size)
{
    const float* pts = (const float*)d_in[0];
    float* out = (float*)d_out;

    static_assert(NN / FPS_T == PPT, "ppt");
    const int smem = 3 * NN * sizeof(float);
    cudaFuncSetAttribute(fps_kernel, cudaFuncAttributeMaxDynamicSharedMemorySize, smem);

    fps_kernel<<<BB, FPS_T, smem>>>(pts, out);
    count_kernel<<<dim3(NREG, BB), 256>>>(pts);
    top4_kernel<<<BB, 32>>>();
    knn_kernel<<<dim3(TOPK, BB), FPS_T>>>(pts, out);
}